// round 15
// baseline (speedup 1.0000x reference)
#include <cuda_runtime.h>
#include <math.h>
#include <stdint.h>

#define BATCH 32
#define EDIM  512
#define HDIM  512
#define G3    1536
#define NTOT  3072      // 2 directions * 3H
#define SMAX  2048
#define CHUNK 2048      // timesteps per launch (1 launch for S=2048)
#define NTHR  512       // Phase B threads per block

#define WPITCH 516
#define HPITCH 516

// Phase A (tensor) tiling
#define KT      16      // k per smem stage
#define NSTAGE  (EDIM / KT)
#define AP      132     // padded pitch for [k][m] smem planes

typedef unsigned long long u64;

// Scratch: gx for all timesteps, both directions: [S][B][3072]  (~805 MB)
__device__ float g_gx[(size_t)SMAX * BATCH * NTOT];
// Double-buffered hidden state: [buf][dir][b][j]
__device__ float g_h[2 * 2 * BATCH * HDIM];
// Per-direction grid barrier state
__device__ unsigned int g_cnt2[2];
__device__ unsigned int g_gen2[2];

// ---------------------------------------------------------------------------
// Init: zero h state and reset barrier state (self-contained per replay)
// ---------------------------------------------------------------------------
__global__ void init_kernel() {
    const int n = 2 * 2 * BATCH * HDIM;
    for (int i = blockIdx.x * blockDim.x + threadIdx.x; i < n;
         i += gridDim.x * blockDim.x)
        g_h[i] = 0.0f;
    if (blockIdx.x == 0 && threadIdx.x == 0) {
        g_cnt2[0] = 0u; g_cnt2[1] = 0u;
        g_gen2[0] = 0u; g_gen2[1] = 0u;
        __threadfence();
    }
}

// ---------------------------------------------------------------------------
// Packed f32x2 helpers (Blackwell FFMA2 path)
// ---------------------------------------------------------------------------
__device__ __forceinline__ void fma_x2(u64& d, u64 a, u64 b) {
    asm("fma.rn.f32x2 %0, %1, %2, %0;" : "+l"(d) : "l"(a), "l"(b));
}
__device__ __forceinline__ float x2_sum(u64 v) {
    float lo = __uint_as_float((unsigned)(v & 0xffffffffull));
    float hi = __uint_as_float((unsigned)(v >> 32));
    return lo + hi;
}

// Acquire load for barrier spin (orders subsequent loads after observation)
__device__ __forceinline__ unsigned ld_acquire_u32(const unsigned* p) {
    unsigned v;
    asm volatile("ld.acquire.gpu.global.u32 %0, [%1];" : "=r"(v) : "l"(p) : "memory");
    return v;
}

// ---------------------------------------------------------------------------
// tf32 helpers (Phase A)
// ---------------------------------------------------------------------------
__device__ __forceinline__ uint32_t f2tf32(float f) {
    uint32_t u;
    asm("cvt.rna.tf32.f32 %0, %1;" : "=r"(u) : "f"(f));
    return u;
}

__device__ __forceinline__ void mma_tf32(float4& d,
                                         const uint32_t a[4],
                                         uint32_t b0, uint32_t b1) {
    asm volatile(
        "mma.sync.aligned.m16n8k8.row.col.f32.tf32.tf32.f32 "
        "{%0,%1,%2,%3}, {%4,%5,%6,%7}, {%8,%9}, {%0,%1,%2,%3};"
        : "+f"(d.x), "+f"(d.y), "+f"(d.z), "+f"(d.w)
        : "r"(a[0]), "r"(a[1]), "r"(a[2]), "r"(a[3]), "r"(b0), "r"(b1));
}

__device__ __forceinline__ void stage_store(float* hiA, float* loA,
                                            int kbase, int col, float4 v) {
    float f[4] = {v.x, v.y, v.z, v.w};
    #pragma unroll
    for (int j = 0; j < 4; ++j) {
        uint32_t hb = f2tf32(f[j]);
        float hf = __uint_as_float(hb);
        uint32_t lb = f2tf32(f[j] - hf);
        hiA[(kbase + j) * AP + col] = hf;
        loA[(kbase + j) * AP + col] = __uint_as_float(lb);
    }
}

// ---------------------------------------------------------------------------
// Phase A: 3xTF32 tensor-core GEMM (unchanged)
// ---------------------------------------------------------------------------
__global__ void __launch_bounds__(256) gemm_gx_tc_kernel(
    const float* __restrict__ X,
    const float* __restrict__ Wf, const float* __restrict__ Wb,
    const float* __restrict__ bf, const float* __restrict__ bb,
    int M)
{
    extern __shared__ float sm[];
    float* Ahi = sm;
    float* Alo = Ahi + 2 * KT * AP;
    float* Bhi = Alo + 2 * KT * AP;
    float* Blo = Bhi + 2 * KT * AP;

    const int tid = threadIdx.x;
    const int n0 = blockIdx.x * 128;
    const int m0 = blockIdx.y * 128;

    const float* Wsel = (n0 < G3) ? Wf : Wb;
    const int    nboff = (n0 < G3) ? n0 : (n0 - G3);
    const float* bsel = (n0 < G3) ? bf : bb;

    const int warp = tid >> 5, lane = tid & 31;
    const int warpM = warp & 3, warpN = warp >> 2;
    const int grp = lane >> 2, tig = lane & 3;
    const int mb = warpM * 32, nb = warpN * 64;

    const int srow = tid >> 2;
    const int skc  = tid & 3;

    float4 C[2][8];
    #pragma unroll
    for (int mt = 0; mt < 2; ++mt)
        #pragma unroll
        for (int nt = 0; nt < 8; ++nt)
            C[mt][nt] = make_float4(0.f, 0.f, 0.f, 0.f);

    const float4 zero4 = make_float4(0.f, 0.f, 0.f, 0.f);

    {
        const int koff = skc * 4;
        float4 ra0 = (m0 + srow      < M) ? *(const float4*)(X + (size_t)(m0 + srow) * EDIM + koff) : zero4;
        float4 ra1 = (m0 + srow + 64 < M) ? *(const float4*)(X + (size_t)(m0 + srow + 64) * EDIM + koff) : zero4;
        float4 rb0 = *(const float4*)(Wsel + (size_t)(nboff + srow) * EDIM + koff);
        float4 rb1 = *(const float4*)(Wsel + (size_t)(nboff + srow + 64) * EDIM + koff);
        stage_store(Ahi, Alo, skc * 4, srow,      ra0);
        stage_store(Ahi, Alo, skc * 4, srow + 64, ra1);
        stage_store(Bhi, Blo, skc * 4, srow,      rb0);
        stage_store(Bhi, Blo, skc * 4, srow + 64, rb1);
    }
    __syncthreads();

    int buf = 0;
    for (int s = 0; s < NSTAGE; ++s) {
        float4 ra0 = zero4, ra1 = zero4, rb0 = zero4, rb1 = zero4;
        const bool more = (s + 1 < NSTAGE);
        if (more) {
            const int koff = (s + 1) * KT + skc * 4;
            if (m0 + srow      < M) ra0 = *(const float4*)(X + (size_t)(m0 + srow) * EDIM + koff);
            if (m0 + srow + 64 < M) ra1 = *(const float4*)(X + (size_t)(m0 + srow + 64) * EDIM + koff);
            rb0 = *(const float4*)(Wsel + (size_t)(nboff + srow) * EDIM + koff);
            rb1 = *(const float4*)(Wsel + (size_t)(nboff + srow + 64) * EDIM + koff);
        }

        #pragma unroll
        for (int ks = 0; ks < 2; ++ks) {
            const float* ah = Ahi + buf * (KT * AP) + (ks * 8) * AP;
            const float* al = Alo + buf * (KT * AP) + (ks * 8) * AP;
            const float* bh = Bhi + buf * (KT * AP) + (ks * 8) * AP;
            const float* bl = Blo + buf * (KT * AP) + (ks * 8) * AP;

            uint32_t Ah[2][4], Al[2][4];
            #pragma unroll
            for (int mt = 0; mt < 2; ++mt) {
                const int base = tig * AP + mb + mt * 16 + grp;
                Ah[mt][0] = __float_as_uint(ah[base]);
                Ah[mt][1] = __float_as_uint(ah[base + 8]);
                Ah[mt][2] = __float_as_uint(ah[base + 4 * AP]);
                Ah[mt][3] = __float_as_uint(ah[base + 4 * AP + 8]);
                Al[mt][0] = __float_as_uint(al[base]);
                Al[mt][1] = __float_as_uint(al[base + 8]);
                Al[mt][2] = __float_as_uint(al[base + 4 * AP]);
                Al[mt][3] = __float_as_uint(al[base + 4 * AP + 8]);
            }
            #pragma unroll
            for (int nt = 0; nt < 8; ++nt) {
                const int bbase = tig * AP + nb + nt * 8 + grp;
                uint32_t Bh0 = __float_as_uint(bh[bbase]);
                uint32_t Bh1 = __float_as_uint(bh[bbase + 4 * AP]);
                uint32_t Bl0 = __float_as_uint(bl[bbase]);
                uint32_t Bl1 = __float_as_uint(bl[bbase + 4 * AP]);
                #pragma unroll
                for (int mt = 0; mt < 2; ++mt) {
                    mma_tf32(C[mt][nt], Ah[mt], Bh0, Bh1);
                    mma_tf32(C[mt][nt], Ah[mt], Bl0, Bl1);
                    mma_tf32(C[mt][nt], Al[mt], Bh0, Bh1);
                }
            }
        }

        if (more) {
            float* dAh = Ahi + (buf ^ 1) * (KT * AP);
            float* dAl = Alo + (buf ^ 1) * (KT * AP);
            float* dBh = Bhi + (buf ^ 1) * (KT * AP);
            float* dBl = Blo + (buf ^ 1) * (KT * AP);
            stage_store(dAh, dAl, skc * 4, srow,      ra0);
            stage_store(dAh, dAl, skc * 4, srow + 64, ra1);
            stage_store(dBh, dBl, skc * 4, srow,      rb0);
            stage_store(dBh, dBl, skc * 4, srow + 64, rb1);
        }
        __syncthreads();
        buf ^= 1;
    }

    #pragma unroll
    for (int nt = 0; nt < 8; ++nt) {
        const int c0 = nb + nt * 8 + 2 * tig;
        const float bias0 = bsel[nboff + c0];
        const float bias1 = bsel[nboff + c0 + 1];
        #pragma unroll
        for (int mt = 0; mt < 2; ++mt) {
            const int r0 = m0 + mb + mt * 16 + grp;
            float4 v = C[mt][nt];
            if (r0 < M) {
                float2 sv = make_float2(v.x + bias0, v.y + bias1);
                *(float2*)&g_gx[(size_t)r0 * NTOT + n0 + c0] = sv;
            }
            const int r1 = r0 + 8;
            if (r1 < M) {
                float2 sv = make_float2(v.z + bias0, v.w + bias1);
                *(float2*)&g_gx[(size_t)r1 * NTOT + n0 + c0] = sv;
            }
        }
    }
}

// ---------------------------------------------------------------------------
// Phase B: chunked persistent recurrence.
// Barrier: tid0 release-arrives; ALL threads acquire-spin on the
// per-direction generation counter and proceed straight into h staging.
// g_h consumer loads use __ldcv (L1-bypass) so freshness never depends on
// an IVALL fence. One less __syncthreads per step, parallel flip detection.
// ---------------------------------------------------------------------------
__global__ void __launch_bounds__(NTHR, 1) gru_chunk_kernel(
    const float* __restrict__ Whf, const float* __restrict__ Whb,
    const float* __restrict__ bhf, const float* __restrict__ bhb,
    float* __restrict__ out, int T, int t0, int nsteps, unsigned gen_base)
{
    extern __shared__ float smem[];
    float* ws  = smem;                    // 24 x WPITCH : Whh slice (r,z,n x 8 cols)
    float* hs  = ws + 24 * WPITCH;        // 32 x HPITCH : full h(prev), [b][k]
    float* red = hs + 32 * HPITCH;        // 16 x 800    : partial-dot reduce
    float* gxs = red + 16 * 800;          // 24 x 33     : [g*8+jj][b]

    const int tid = threadIdx.x;
    const int dir = blockIdx.x >> 6;
    const int cb  = blockIdx.x & 63;
    const int j0  = cb * 8;

    const float* W  = dir ? Whb : Whf;
    const float* bh = dir ? bhb : bhf;

    // --- load Whh slice once per launch (3072 float4, 6 iters of 512) ---
    #pragma unroll
    for (int it = 0; it < 6; ++it) {
        int idx4 = it * NTHR + tid;         // rr*128 + k4
        int rr = idx4 >> 7;                 // 0..23 : g*8 + jj
        int k4 = idx4 & 127;
        int g  = rr >> 3;
        int jjv = rr & 7;
        float4 v = *(const float4*)(W + (size_t)(g * 512 + j0 + jjv) * HDIM + k4 * 4);
        *(float4*)(ws + rr * WPITCH + k4 * 4) = v;
    }

    // thread roles
    const int jj = tid & 7;          // partial-dot: weight column
    const int bg = (tid >> 3) & 3;   // partial-dot: batch group (b = bg + 4*i)
    const int kq = tid >> 5;         // partial-dot: k partition (16 x 32k)
    const int ejj = (tid >> 5) & 7;  // epilogue: column (tid < 256)
    const int eb  = tid & 31;        // epilogue: batch

    // per-thread gate biases
    const float br_ = bh[0 * 512 + j0 + ejj];
    const float bz_ = bh[1 * 512 + j0 + ejj];
    const float bn_ = bh[2 * 512 + j0 + ejj];

    // gx prefetch mapping: each thread covers linear idx = tid and (tid+NTHR if <768)
    const int p0 = tid;
    const int p1 = tid + NTHR;             // only valid if < 768
    const int p0_b = p0 / 24, p0_r = p0 % 24;
    const int p1_b = p1 / 24, p1_r = p1 % 24;
    const int p0_g = p0_r >> 3, p0_j = p0_r & 7;
    const int p1_g = p1_r >> 3, p1_j = p1_r & 7;
    const bool p1v = (p1 < 768);

    // --- prologue: prefetch gx for step t0 ---
    float pf0, pf1 = 0.f;
    {
        const int tt = dir ? (T - 1 - t0) : t0;
        const float* gp = g_gx + (size_t)tt * (BATCH * NTOT) + dir * G3 + j0;
        pf0 = gp[(size_t)p0_b * NTOT + p0_g * 512 + p0_j];
        if (p1v) pf1 = gp[(size_t)p1_b * NTOT + p1_g * 512 + p1_j];
    }

    for (int s = 0; s < nsteps; ++s) {
        const int t = t0 + s;
        const int phase = t & 1;

        // --- stage h(prev) into smem, [b][k]; L1-bypass loads (fresh L2) ---
        {
            const float4* hp = (const float4*)(g_h + (size_t)(phase * 2 + dir) * BATCH * HDIM);
            #pragma unroll
            for (int it = 0; it < 8; ++it) {
                int idx4 = it * NTHR + tid;     // b*128 + k4
                int b  = idx4 >> 7;
                int k4 = idx4 & 127;
                float4 v = __ldcv(hp + idx4);
                *(float4*)(hs + b * HPITCH + k4 * 4) = v;
            }
        }
        // --- store prefetched gx into smem ---
        gxs[p0_r * 33 + p0_b] = pf0;
        if (p1v) gxs[p1_r * 33 + p1_b] = pf1;
        __syncthreads();

        // --- partial dots: thread = (jj, bg, kq); 3 gates x 8 batches, 32 k ---
        u64 a0[8], a1[8], a2[8];
        #pragma unroll
        for (int i = 0; i < 8; ++i) { a0[i] = 0ull; a1[i] = 0ull; a2[i] = 0ull; }
        const float* wr  = ws + jj * WPITCH + kq * 32;
        const float* wz  = ws + (8 + jj) * WPITCH + kq * 32;
        const float* wn  = ws + (16 + jj) * WPITCH + kq * 32;
        const float* hb0 = hs + bg * HPITCH + kq * 32;
        #pragma unroll
        for (int k4 = 0; k4 < 8; ++k4) {
            double2 vr = *(const double2*)(wr + k4 * 4);
            double2 vz = *(const double2*)(wz + k4 * 4);
            double2 vn = *(const double2*)(wn + k4 * 4);
            u64 wr0 = __double_as_longlong(vr.x), wr1 = __double_as_longlong(vr.y);
            u64 wz0 = __double_as_longlong(vz.x), wz1 = __double_as_longlong(vz.y);
            u64 wn0 = __double_as_longlong(vn.x), wn1 = __double_as_longlong(vn.y);
            #pragma unroll
            for (int i = 0; i < 8; ++i) {
                double2 hv = *(const double2*)(hb0 + i * (4 * HPITCH) + k4 * 4);
                u64 h0 = __double_as_longlong(hv.x), h1 = __double_as_longlong(hv.y);
                fma_x2(a0[i], wr0, h0);
                fma_x2(a0[i], wr1, h1);
                fma_x2(a1[i], wz0, h0);
                fma_x2(a1[i], wz1, h1);
                fma_x2(a2[i], wn0, h0);
                fma_x2(a2[i], wn1, h1);
            }
        }
        #pragma unroll
        for (int i = 0; i < 8; ++i) {
            int b = bg + 4 * i;
            red[kq * 800 + b * 25 + jj]      = x2_sum(a0[i]);
            red[kq * 800 + b * 25 + 8 + jj]  = x2_sum(a1[i]);
            red[kq * 800 + b * 25 + 16 + jj] = x2_sum(a2[i]);
        }
        __syncthreads();

        // --- reduce over 16 kq + gate math + h update (tid < 256) ---
        if (tid < 256) {
            float hr = 0.f, hz = 0.f, hn = 0.f;
            #pragma unroll
            for (int q = 0; q < 16; ++q) {
                const float* rp = red + q * 800 + eb * 25;
                hr += rp[ejj];
                hz += rp[8 + ejj];
                hn += rp[16 + ejj];
            }
            float xr = gxs[(0 * 8 + ejj) * 33 + eb];
            float xz = gxs[(1 * 8 + ejj) * 33 + eb];
            float xn = gxs[(2 * 8 + ejj) * 33 + eb];
            float r = 1.f / (1.f + expf(-(xr + hr + br_)));
            float z = 1.f / (1.f + expf(-(xz + hz + bz_)));
            float n = tanhf(xn + r * (hn + bn_));
            float hold = hs[eb * HPITCH + j0 + ejj];
            float hnew = (1.f - z) * n + z * hold;

            g_h[(size_t)(((1 - phase) * 2 + dir) * BATCH + eb) * HDIM + j0 + ejj] = hnew;
            if (t == T - 1)
                out[eb * (2 * HDIM) + dir * HDIM + j0 + ejj] = hnew;
        }

        // --- prefetch gx for next step (independent of h; before barrier) ---
        if (s + 1 < nsteps) {
            const int t2 = t + 1;
            const int tt2 = dir ? (T - 1 - t2) : t2;
            const float* gp2 = g_gx + (size_t)tt2 * (BATCH * NTOT) + dir * G3 + j0;
            pf0 = gp2[(size_t)p0_b * NTOT + p0_g * 512 + p0_j];
            if (p1v) pf1 = gp2[(size_t)p1_b * NTOT + p1_g * 512 + p1_j];
        }

        // --- per-direction barrier: tid0 release-arrive, ALL threads spin ---
        if (s < nsteps - 1) {
            __syncthreads();               // all h stores done before arrive
            if (tid == 0) {
                __threadfence();
                unsigned prev = atomicAdd(&g_cnt2[dir], 1u);
                if (prev == 63u) {
                    g_cnt2[dir] = 0u;
                    __threadfence();
                    atomicAdd(&g_gen2[dir], 1u);
                }
            }
            const unsigned want = gen_base + (unsigned)(s + 1);
            while (ld_acquire_u32(&g_gen2[dir]) < want) __nanosleep(32);
        }
    }
}

// ---------------------------------------------------------------------------
// kernel_launch
// ---------------------------------------------------------------------------
extern "C" void kernel_launch(void* const* d_in, const int* in_sizes, int n_in,
                              void* d_out, int out_size) {
    const float* X      = (const float*)d_in[1];
    const float* Wihf   = (const float*)d_in[2];
    const float* Whhf   = (const float*)d_in[3];
    const float* bihf   = (const float*)d_in[4];
    const float* bhhf   = (const float*)d_in[5];
    const float* Wihb   = (const float*)d_in[6];
    const float* Whhb   = (const float*)d_in[7];
    const float* bihb   = (const float*)d_in[8];
    const float* bhhb   = (const float*)d_in[9];
    float* out = (float*)d_out;

    int S = in_sizes[1] / (BATCH * EDIM);
    if (S > SMAX) S = SMAX;
    int M = S * BATCH;
    int T = S;

    init_kernel<<<32, 256>>>();

    // Phase A: 3xTF32 tensor-core GEMM
    size_t smem_a = (size_t)(4 * 2 * KT * AP) * sizeof(float);  // 67584 B
    cudaFuncSetAttribute(gemm_gx_tc_kernel,
                         cudaFuncAttributeMaxDynamicSharedMemorySize, (int)smem_a);
    dim3 grid(NTOT / 128, (M + 127) / 128);
    gemm_gx_tc_kernel<<<grid, 256, smem_a>>>(X, Wihf, Wihb, bihf, bihb, M);

    // Phase B: chunked persistent recurrence (512 threads, 1 launch for S=2048)
    size_t smem_b = (size_t)(24 * WPITCH + 32 * HPITCH + 16 * 800 + 24 * 33 + 8)
                    * sizeof(float);
    cudaFuncSetAttribute(gru_chunk_kernel,
                         cudaFuncAttributeMaxDynamicSharedMemorySize, (int)smem_b);
    unsigned gen_base = 0;
    for (int t0 = 0; t0 < T; t0 += CHUNK) {
        int ns = (T - t0 < CHUNK) ? (T - t0) : CHUNK;
        gru_chunk_kernel<<<128, NTHR, smem_b>>>(Whhf, Whhb, bhhf, bhhb, out,
                                                T, t0, ns, gen_base);
        gen_base += (unsigned)(ns - 1);
    }
}

// round 16
// speedup vs baseline: 1.0426x; 1.0426x over previous
#include <cuda_runtime.h>
#include <math.h>
#include <stdint.h>

#define BATCH 32
#define EDIM  512
#define HDIM  512
#define G3    1536
#define NTOT  3072      // 2 directions * 3H
#define SMAX  2048
#define CHUNK 2048      // timesteps per launch (1 launch for S=2048)
#define NTHR  512       // Phase B threads per block

#define WPITCH 516
#define HPITCH 516

// Phase A (tensor) tiling
#define KT      16      // k per smem stage
#define NSTAGE  (EDIM / KT)
#define AP      132     // padded pitch for [k][m] smem planes

typedef unsigned long long u64;

// Scratch: gx for all timesteps, both directions: [S][B][3072]  (~805 MB)
__device__ float g_gx[(size_t)SMAX * BATCH * NTOT];
// Double-buffered hidden state: [buf][dir][b][j]
__device__ float g_h[2 * 2 * BATCH * HDIM];
// Per-direction grid barrier state
__device__ unsigned int g_cnt2[2];
__device__ unsigned int g_gen2[2];

// ---------------------------------------------------------------------------
// Init: zero h state and reset barrier state (self-contained per replay)
// ---------------------------------------------------------------------------
__global__ void init_kernel() {
    const int n = 2 * 2 * BATCH * HDIM;
    for (int i = blockIdx.x * blockDim.x + threadIdx.x; i < n;
         i += gridDim.x * blockDim.x)
        g_h[i] = 0.0f;
    if (blockIdx.x == 0 && threadIdx.x == 0) {
        g_cnt2[0] = 0u; g_cnt2[1] = 0u;
        g_gen2[0] = 0u; g_gen2[1] = 0u;
        __threadfence();
    }
}

// ---------------------------------------------------------------------------
// Packed f32x2 helpers (Blackwell FFMA2 path)
// ---------------------------------------------------------------------------
__device__ __forceinline__ void fma_x2(u64& d, u64 a, u64 b) {
    asm("fma.rn.f32x2 %0, %1, %2, %0;" : "+l"(d) : "l"(a), "l"(b));
}
__device__ __forceinline__ float x2_sum(u64 v) {
    float lo = __uint_as_float((unsigned)(v & 0xffffffffull));
    float hi = __uint_as_float((unsigned)(v >> 32));
    return lo + hi;
}

// ---------------------------------------------------------------------------
// tf32 helpers (Phase A)
// ---------------------------------------------------------------------------
__device__ __forceinline__ uint32_t f2tf32(float f) {
    uint32_t u;
    asm("cvt.rna.tf32.f32 %0, %1;" : "=r"(u) : "f"(f));
    return u;
}

__device__ __forceinline__ void mma_tf32(float4& d,
                                         const uint32_t a[4],
                                         uint32_t b0, uint32_t b1) {
    asm volatile(
        "mma.sync.aligned.m16n8k8.row.col.f32.tf32.tf32.f32 "
        "{%0,%1,%2,%3}, {%4,%5,%6,%7}, {%8,%9}, {%0,%1,%2,%3};"
        : "+f"(d.x), "+f"(d.y), "+f"(d.z), "+f"(d.w)
        : "r"(a[0]), "r"(a[1]), "r"(a[2]), "r"(a[3]), "r"(b0), "r"(b1));
}

__device__ __forceinline__ void stage_store(float* hiA, float* loA,
                                            int kbase, int col, float4 v) {
    float f[4] = {v.x, v.y, v.z, v.w};
    #pragma unroll
    for (int j = 0; j < 4; ++j) {
        uint32_t hb = f2tf32(f[j]);
        float hf = __uint_as_float(hb);
        uint32_t lb = f2tf32(f[j] - hf);
        hiA[(kbase + j) * AP + col] = hf;
        loA[(kbase + j) * AP + col] = __uint_as_float(lb);
    }
}

// ---------------------------------------------------------------------------
// Phase A: 3xTF32 tensor-core GEMM (unchanged)
// ---------------------------------------------------------------------------
__global__ void __launch_bounds__(256) gemm_gx_tc_kernel(
    const float* __restrict__ X,
    const float* __restrict__ Wf, const float* __restrict__ Wb,
    const float* __restrict__ bf, const float* __restrict__ bb,
    int M)
{
    extern __shared__ float sm[];
    float* Ahi = sm;
    float* Alo = Ahi + 2 * KT * AP;
    float* Bhi = Alo + 2 * KT * AP;
    float* Blo = Bhi + 2 * KT * AP;

    const int tid = threadIdx.x;
    const int n0 = blockIdx.x * 128;
    const int m0 = blockIdx.y * 128;

    const float* Wsel = (n0 < G3) ? Wf : Wb;
    const int    nboff = (n0 < G3) ? n0 : (n0 - G3);
    const float* bsel = (n0 < G3) ? bf : bb;

    const int warp = tid >> 5, lane = tid & 31;
    const int warpM = warp & 3, warpN = warp >> 2;
    const int grp = lane >> 2, tig = lane & 3;
    const int mb = warpM * 32, nb = warpN * 64;

    const int srow = tid >> 2;
    const int skc  = tid & 3;

    float4 C[2][8];
    #pragma unroll
    for (int mt = 0; mt < 2; ++mt)
        #pragma unroll
        for (int nt = 0; nt < 8; ++nt)
            C[mt][nt] = make_float4(0.f, 0.f, 0.f, 0.f);

    const float4 zero4 = make_float4(0.f, 0.f, 0.f, 0.f);

    {
        const int koff = skc * 4;
        float4 ra0 = (m0 + srow      < M) ? *(const float4*)(X + (size_t)(m0 + srow) * EDIM + koff) : zero4;
        float4 ra1 = (m0 + srow + 64 < M) ? *(const float4*)(X + (size_t)(m0 + srow + 64) * EDIM + koff) : zero4;
        float4 rb0 = *(const float4*)(Wsel + (size_t)(nboff + srow) * EDIM + koff);
        float4 rb1 = *(const float4*)(Wsel + (size_t)(nboff + srow + 64) * EDIM + koff);
        stage_store(Ahi, Alo, skc * 4, srow,      ra0);
        stage_store(Ahi, Alo, skc * 4, srow + 64, ra1);
        stage_store(Bhi, Blo, skc * 4, srow,      rb0);
        stage_store(Bhi, Blo, skc * 4, srow + 64, rb1);
    }
    __syncthreads();

    int buf = 0;
    for (int s = 0; s < NSTAGE; ++s) {
        float4 ra0 = zero4, ra1 = zero4, rb0 = zero4, rb1 = zero4;
        const bool more = (s + 1 < NSTAGE);
        if (more) {
            const int koff = (s + 1) * KT + skc * 4;
            if (m0 + srow      < M) ra0 = *(const float4*)(X + (size_t)(m0 + srow) * EDIM + koff);
            if (m0 + srow + 64 < M) ra1 = *(const float4*)(X + (size_t)(m0 + srow + 64) * EDIM + koff);
            rb0 = *(const float4*)(Wsel + (size_t)(nboff + srow) * EDIM + koff);
            rb1 = *(const float4*)(Wsel + (size_t)(nboff + srow + 64) * EDIM + koff);
        }

        #pragma unroll
        for (int ks = 0; ks < 2; ++ks) {
            const float* ah = Ahi + buf * (KT * AP) + (ks * 8) * AP;
            const float* al = Alo + buf * (KT * AP) + (ks * 8) * AP;
            const float* bh = Bhi + buf * (KT * AP) + (ks * 8) * AP;
            const float* bl = Blo + buf * (KT * AP) + (ks * 8) * AP;

            uint32_t Ah[2][4], Al[2][4];
            #pragma unroll
            for (int mt = 0; mt < 2; ++mt) {
                const int base = tig * AP + mb + mt * 16 + grp;
                Ah[mt][0] = __float_as_uint(ah[base]);
                Ah[mt][1] = __float_as_uint(ah[base + 8]);
                Ah[mt][2] = __float_as_uint(ah[base + 4 * AP]);
                Ah[mt][3] = __float_as_uint(ah[base + 4 * AP + 8]);
                Al[mt][0] = __float_as_uint(al[base]);
                Al[mt][1] = __float_as_uint(al[base + 8]);
                Al[mt][2] = __float_as_uint(al[base + 4 * AP]);
                Al[mt][3] = __float_as_uint(al[base + 4 * AP + 8]);
            }
            #pragma unroll
            for (int nt = 0; nt < 8; ++nt) {
                const int bbase = tig * AP + nb + nt * 8 + grp;
                uint32_t Bh0 = __float_as_uint(bh[bbase]);
                uint32_t Bh1 = __float_as_uint(bh[bbase + 4 * AP]);
                uint32_t Bl0 = __float_as_uint(bl[bbase]);
                uint32_t Bl1 = __float_as_uint(bl[bbase + 4 * AP]);
                #pragma unroll
                for (int mt = 0; mt < 2; ++mt) {
                    mma_tf32(C[mt][nt], Ah[mt], Bh0, Bh1);
                    mma_tf32(C[mt][nt], Ah[mt], Bl0, Bl1);
                    mma_tf32(C[mt][nt], Al[mt], Bh0, Bh1);
                }
            }
        }

        if (more) {
            float* dAh = Ahi + (buf ^ 1) * (KT * AP);
            float* dAl = Alo + (buf ^ 1) * (KT * AP);
            float* dBh = Bhi + (buf ^ 1) * (KT * AP);
            float* dBl = Blo + (buf ^ 1) * (KT * AP);
            stage_store(dAh, dAl, skc * 4, srow,      ra0);
            stage_store(dAh, dAl, skc * 4, srow + 64, ra1);
            stage_store(dBh, dBl, skc * 4, srow,      rb0);
            stage_store(dBh, dBl, skc * 4, srow + 64, rb1);
        }
        __syncthreads();
        buf ^= 1;
    }

    #pragma unroll
    for (int nt = 0; nt < 8; ++nt) {
        const int c0 = nb + nt * 8 + 2 * tig;
        const float bias0 = bsel[nboff + c0];
        const float bias1 = bsel[nboff + c0 + 1];
        #pragma unroll
        for (int mt = 0; mt < 2; ++mt) {
            const int r0 = m0 + mb + mt * 16 + grp;
            float4 v = C[mt][nt];
            if (r0 < M) {
                float2 sv = make_float2(v.x + bias0, v.y + bias1);
                *(float2*)&g_gx[(size_t)r0 * NTOT + n0 + c0] = sv;
            }
            const int r1 = r0 + 8;
            if (r1 < M) {
                float2 sv = make_float2(v.z + bias0, v.w + bias1);
                *(float2*)&g_gx[(size_t)r1 * NTOT + n0 + c0] = sv;
            }
        }
    }
}

// ---------------------------------------------------------------------------
// Phase B: single-launch persistent recurrence.
// Barrier reverted to the PROVEN R12 form: tid0 equality-spin on the gen
// counter (128 pollers chip-wide, no L2 storm) + __syncthreads release.
// h staging back to plain LDG. gx(t+1) prefetch kept. Monotonic gen across
// the single launch.
// ---------------------------------------------------------------------------
__global__ void __launch_bounds__(NTHR, 1) gru_chunk_kernel(
    const float* __restrict__ Whf, const float* __restrict__ Whb,
    const float* __restrict__ bhf, const float* __restrict__ bhb,
    float* __restrict__ out, int T, int t0, int nsteps)
{
    extern __shared__ float smem[];
    float* ws  = smem;                    // 24 x WPITCH : Whh slice (r,z,n x 8 cols)
    float* hs  = ws + 24 * WPITCH;        // 32 x HPITCH : full h(prev), [b][k]
    float* red = hs + 32 * HPITCH;        // 16 x 800    : partial-dot reduce
    float* gxs = red + 16 * 800;          // 24 x 33     : [g*8+jj][b]

    const int tid = threadIdx.x;
    const int dir = blockIdx.x >> 6;
    const int cb  = blockIdx.x & 63;
    const int j0  = cb * 8;

    const float* W  = dir ? Whb : Whf;
    const float* bh = dir ? bhb : bhf;

    // --- load Whh slice once per launch (3072 float4, 6 iters of 512) ---
    #pragma unroll
    for (int it = 0; it < 6; ++it) {
        int idx4 = it * NTHR + tid;         // rr*128 + k4
        int rr = idx4 >> 7;                 // 0..23 : g*8 + jj
        int k4 = idx4 & 127;
        int g  = rr >> 3;
        int jjv = rr & 7;
        float4 v = *(const float4*)(W + (size_t)(g * 512 + j0 + jjv) * HDIM + k4 * 4);
        *(float4*)(ws + rr * WPITCH + k4 * 4) = v;
    }

    // thread roles
    const int jj = tid & 7;          // partial-dot: weight column
    const int bg = (tid >> 3) & 3;   // partial-dot: batch group (b = bg + 4*i)
    const int kq = tid >> 5;         // partial-dot: k partition (16 x 32k)
    const int ejj = (tid >> 5) & 7;  // epilogue: column (tid < 256)
    const int eb  = tid & 31;        // epilogue: batch

    // per-thread gate biases
    const float br_ = bh[0 * 512 + j0 + ejj];
    const float bz_ = bh[1 * 512 + j0 + ejj];
    const float bn_ = bh[2 * 512 + j0 + ejj];

    // gx prefetch mapping: each thread covers linear idx = tid and (tid+NTHR if <768)
    const int p0 = tid;
    const int p1 = tid + NTHR;             // only valid if < 768
    const int p0_b = p0 / 24, p0_r = p0 % 24;
    const int p1_b = p1 / 24, p1_r = p1 % 24;
    const int p0_g = p0_r >> 3, p0_j = p0_r & 7;
    const int p1_g = p1_r >> 3, p1_j = p1_r & 7;
    const bool p1v = (p1 < 768);

    // --- prologue: prefetch gx for step t0 ---
    float pf0, pf1 = 0.f;
    {
        const int tt = dir ? (T - 1 - t0) : t0;
        const float* gp = g_gx + (size_t)tt * (BATCH * NTOT) + dir * G3 + j0;
        pf0 = gp[(size_t)p0_b * NTOT + p0_g * 512 + p0_j];
        if (p1v) pf1 = gp[(size_t)p1_b * NTOT + p1_g * 512 + p1_j];
    }

    for (int s = 0; s < nsteps; ++s) {
        const int t = t0 + s;
        const int phase = t & 1;

        // --- stage h(prev) into smem, layout [b][k] (plain LDG, as R12) ---
        {
            const float4* hp = (const float4*)(g_h + (size_t)(phase * 2 + dir) * BATCH * HDIM);
            #pragma unroll
            for (int it = 0; it < 8; ++it) {
                int idx4 = it * NTHR + tid;     // b*128 + k4
                int b  = idx4 >> 7;
                int k4 = idx4 & 127;
                float4 v = hp[idx4];
                *(float4*)(hs + b * HPITCH + k4 * 4) = v;
            }
        }
        // --- store prefetched gx into smem ---
        gxs[p0_r * 33 + p0_b] = pf0;
        if (p1v) gxs[p1_r * 33 + p1_b] = pf1;
        __syncthreads();

        // --- partial dots: thread = (jj, bg, kq); 3 gates x 8 batches, 32 k ---
        u64 a0[8], a1[8], a2[8];
        #pragma unroll
        for (int i = 0; i < 8; ++i) { a0[i] = 0ull; a1[i] = 0ull; a2[i] = 0ull; }
        const float* wr  = ws + jj * WPITCH + kq * 32;
        const float* wz  = ws + (8 + jj) * WPITCH + kq * 32;
        const float* wn  = ws + (16 + jj) * WPITCH + kq * 32;
        const float* hb0 = hs + bg * HPITCH + kq * 32;
        #pragma unroll
        for (int k4 = 0; k4 < 8; ++k4) {
            double2 vr = *(const double2*)(wr + k4 * 4);
            double2 vz = *(const double2*)(wz + k4 * 4);
            double2 vn = *(const double2*)(wn + k4 * 4);
            u64 wr0 = __double_as_longlong(vr.x), wr1 = __double_as_longlong(vr.y);
            u64 wz0 = __double_as_longlong(vz.x), wz1 = __double_as_longlong(vz.y);
            u64 wn0 = __double_as_longlong(vn.x), wn1 = __double_as_longlong(vn.y);
            #pragma unroll
            for (int i = 0; i < 8; ++i) {
                double2 hv = *(const double2*)(hb0 + i * (4 * HPITCH) + k4 * 4);
                u64 h0 = __double_as_longlong(hv.x), h1 = __double_as_longlong(hv.y);
                fma_x2(a0[i], wr0, h0);
                fma_x2(a0[i], wr1, h1);
                fma_x2(a1[i], wz0, h0);
                fma_x2(a1[i], wz1, h1);
                fma_x2(a2[i], wn0, h0);
                fma_x2(a2[i], wn1, h1);
            }
        }
        #pragma unroll
        for (int i = 0; i < 8; ++i) {
            int b = bg + 4 * i;
            red[kq * 800 + b * 25 + jj]      = x2_sum(a0[i]);
            red[kq * 800 + b * 25 + 8 + jj]  = x2_sum(a1[i]);
            red[kq * 800 + b * 25 + 16 + jj] = x2_sum(a2[i]);
        }
        __syncthreads();

        // --- reduce over 16 kq + gate math + h update (tid < 256) ---
        if (tid < 256) {
            float hr = 0.f, hz = 0.f, hn = 0.f;
            #pragma unroll
            for (int q = 0; q < 16; ++q) {
                const float* rp = red + q * 800 + eb * 25;
                hr += rp[ejj];
                hz += rp[8 + ejj];
                hn += rp[16 + ejj];
            }
            float xr = gxs[(0 * 8 + ejj) * 33 + eb];
            float xz = gxs[(1 * 8 + ejj) * 33 + eb];
            float xn = gxs[(2 * 8 + ejj) * 33 + eb];
            float r = 1.f / (1.f + expf(-(xr + hr + br_)));
            float z = 1.f / (1.f + expf(-(xz + hz + bz_)));
            float n = tanhf(xn + r * (hn + bn_));
            float hold = hs[eb * HPITCH + j0 + ejj];
            float hnew = (1.f - z) * n + z * hold;

            g_h[(size_t)(((1 - phase) * 2 + dir) * BATCH + eb) * HDIM + j0 + ejj] = hnew;
            if (t == T - 1)
                out[eb * (2 * HDIM) + dir * HDIM + j0 + ejj] = hnew;
        }

        // --- prefetch gx for next step (independent of h; before barrier) ---
        if (s + 1 < nsteps) {
            const int t2 = t + 1;
            const int tt2 = dir ? (T - 1 - t2) : t2;
            const float* gp2 = g_gx + (size_t)tt2 * (BATCH * NTOT) + dir * G3 + j0;
            pf0 = gp2[(size_t)p0_b * NTOT + p0_g * 512 + p0_j];
            if (p1v) pf1 = gp2[(size_t)p1_b * NTOT + p1_g * 512 + p1_j];
        }

        // --- per-direction grid barrier (R12 form: tid0 spins, block syncs) ---
        if (s < nsteps - 1) {
            __syncthreads();
            if (tid == 0) {
                __threadfence();
                unsigned int g = *((volatile unsigned int*)&g_gen2[dir]);
                unsigned int prev = atomicAdd(&g_cnt2[dir], 1u);
                if (prev == 63u) {
                    g_cnt2[dir] = 0u;
                    __threadfence();
                    atomicAdd(&g_gen2[dir], 1u);
                } else {
                    while (*((volatile unsigned int*)&g_gen2[dir]) == g) __nanosleep(32);
                }
                __threadfence();
            }
            __syncthreads();
        }
    }
}

// ---------------------------------------------------------------------------
// kernel_launch
// ---------------------------------------------------------------------------
extern "C" void kernel_launch(void* const* d_in, const int* in_sizes, int n_in,
                              void* d_out, int out_size) {
    const float* X      = (const float*)d_in[1];
    const float* Wihf   = (const float*)d_in[2];
    const float* Whhf   = (const float*)d_in[3];
    const float* bihf   = (const float*)d_in[4];
    const float* bhhf   = (const float*)d_in[5];
    const float* Wihb   = (const float*)d_in[6];
    const float* Whhb   = (const float*)d_in[7];
    const float* bihb   = (const float*)d_in[8];
    const float* bhhb   = (const float*)d_in[9];
    float* out = (float*)d_out;

    int S = in_sizes[1] / (BATCH * EDIM);
    if (S > SMAX) S = SMAX;
    int M = S * BATCH;
    int T = S;

    init_kernel<<<32, 256>>>();

    // Phase A: 3xTF32 tensor-core GEMM
    size_t smem_a = (size_t)(4 * 2 * KT * AP) * sizeof(float);  // 67584 B
    cudaFuncSetAttribute(gemm_gx_tc_kernel,
                         cudaFuncAttributeMaxDynamicSharedMemorySize, (int)smem_a);
    dim3 grid(NTOT / 128, (M + 127) / 128);
    gemm_gx_tc_kernel<<<grid, 256, smem_a>>>(X, Wihf, Wihb, bihf, bihb, M);

    // Phase B: single-launch persistent recurrence (512 threads)
    size_t smem_b = (size_t)(24 * WPITCH + 32 * HPITCH + 16 * 800 + 24 * 33 + 8)
                    * sizeof(float);
    cudaFuncSetAttribute(gru_chunk_kernel,
                         cudaFuncAttributeMaxDynamicSharedMemorySize, (int)smem_b);
    for (int t0 = 0; t0 < T; t0 += CHUNK) {
        int ns = (T - t0 < CHUNK) ? (T - t0) : CHUNK;
        gru_chunk_kernel<<<128, NTHR, smem_b>>>(Whhf, Whhb, bhhf, bhhb, out, T, t0, ns);
    }
}